// round 2
// baseline (speedup 1.0000x reference)
#include <cuda_runtime.h>

// ---------------- problem constants ----------------
#define NBATCH 512
#define HID    512
#define GATES  2048           // 4*HID
#define DDIM   9
#define TENC   257            // encode steps (T+1)
#define TDEC   256            // decode steps
#define NSTEPS 513            // TENC + TDEC

// ---------------- tiling ----------------
#define MB 4                  // batch blocks
#define JB 32                 // hidden-unit blocks
#define NCTA (MB*JB)          // 128 CTAs, 1 per SM, all resident
#define MT 128                // batch rows per CTA
#define JT 16                 // hidden units per CTA
#define CT 64                 // gate columns per CTA = 4*JT
#define KC 32                 // k-chunk
#define NCHUNK (HID/KC)       // 16
#define NTHREADS 256

#define HS_STRIDE 130         // padded row stride for h tile (conflict-free, even for 8B loads)
#define HS_BUF (KC*HS_STRIDE)
#define XS_STRIDE 12

// smem layout in floats
#define WS_OFF   0
#define HS_OFF   (WS_OFF + HID*CT)            // 32768
#define XS_OFF   (HS_OFF + 2*HS_BUF)          // +8320
#define WIH_OFF  (XS_OFF + MT*XS_STRIDE)      // +1536
#define BIAS_OFF (WIH_OFF + CT*XS_STRIDE)     // +768
#define SMEM_FLOATS (BIAS_OFF + CT)
#define SMEM_BYTES  (SMEM_FLOATS*4)           // 173,824 B

typedef unsigned long long ull;

// ---------------- device globals ----------------
__device__ __align__(16) float g_h[2][NBATCH*HID];   // double-buffered hidden state
__device__ unsigned g_cnt = 0;
__device__ unsigned g_gen = 0;

// ---------------- helpers ----------------
__device__ __forceinline__ float sigf(float x) { return 1.0f / (1.0f + __expf(-x)); }

__device__ __forceinline__ ull pack2(float lo, float hi) {
    ull r; asm("mov.b64 %0, {%1,%2};" : "=l"(r) : "f"(lo), "f"(hi)); return r;
}
__device__ __forceinline__ void unpack2(ull v, float& lo, float& hi) {
    asm("mov.b64 {%0,%1}, %2;" : "=f"(lo), "=f"(hi) : "l"(v));
}
__device__ __forceinline__ ull dup2(float x) {
    ull r; asm("mov.b64 %0, {%1,%1};" : "=l"(r) : "f"(x)); return r;
}
__device__ __forceinline__ void ffma2(ull& acc, ull a, ull b) {
    asm("fma.rn.f32x2 %0, %1, %2, %0;" : "+l"(acc) : "l"(a), "l"(b));
}

__device__ __forceinline__ void grid_sync() {
    __syncthreads();
    if (threadIdx.x == 0) {
        __threadfence();
        volatile unsigned* genp = &g_gen;
        unsigned target = *genp + 1u;
        if (atomicAdd(&g_cnt, 1u) == NCTA - 1u) {
            atomicExch(&g_cnt, 0u);
            __threadfence();
            atomicExch(&g_gen, target);
        } else {
            while ((int)(*genp - target) < 0) { }
        }
        __threadfence();
    }
    __syncthreads();
}

// prefetch one 128x32 chunk of h into registers (coalesced float4, L2 path)
__device__ __forceinline__ void ldg_chunk(float4* pf, const float* __restrict__ hin,
                                          int m0, int k0, int tid) {
    int rr = tid >> 3;              // 0..31
    int k4 = (tid & 7) << 2;        // 0,4,...,28
    const float4* base = (const float4*)(hin + (size_t)(m0 + rr) * HID + k0 + k4);
#pragma unroll
    for (int i = 0; i < 4; ++i)
        pf[i] = __ldcg(base + (size_t)i * 32 * (HID / 4));
}
// store chunk transposed into smem: hs[k][row], stride 130 (conflict-free-ish)
__device__ __forceinline__ void sts_chunk(const float4* pf, float* hbuf, int tid) {
    int rr = tid >> 3;
    int k4 = (tid & 7) << 2;
#pragma unroll
    for (int i = 0; i < 4; ++i) {
        int row = rr + i * 32;
        hbuf[(k4 + 0) * HS_STRIDE + row] = pf[i].x;
        hbuf[(k4 + 1) * HS_STRIDE + row] = pf[i].y;
        hbuf[(k4 + 2) * HS_STRIDE + row] = pf[i].z;
        hbuf[(k4 + 3) * HS_STRIDE + row] = pf[i].w;
    }
}

// FC head: 4 rows x 9 outputs per CTA, one output per warp-slot, lane-parallel over k
__device__ __forceinline__ void fc_out(const float* __restrict__ h,
                                       const float* __restrict__ fcW,
                                       const float* __restrict__ fcb,
                                       float* __restrict__ out,
                                       int n0, int td, int wid, int lane) {
    for (int o = wid; o < 4 * DDIM; o += 8) {
        int rr = o / DDIM, d = o - rr * DDIM;
        int n = n0 + rr;
        const float* hr = h + (size_t)n * HID;
        const float* wr = fcW + d * HID;
        float s = 0.0f;
#pragma unroll
        for (int j = 0; j < 16; ++j)
            s += __ldcg(hr + j * 32 + lane) * wr[j * 32 + lane];
#pragma unroll
        for (int off = 16; off; off >>= 1)
            s += __shfl_xor_sync(0xffffffffu, s, off);
        if (lane == 0)
            out[((size_t)n * TDEC + td) * DDIM + d] = sigf(s + fcb[d]);
    }
}

// ---------------- persistent kernel ----------------
__global__ void __launch_bounds__(NTHREADS, 1)
lstm_kernel(const float* __restrict__ x, const float* __restrict__ W_ih,
            const float* __restrict__ W_hh, const float* __restrict__ b_ih,
            const float* __restrict__ b_hh, const float* __restrict__ fcW,
            const float* __restrict__ fcb, const float* __restrict__ h0,
            const float* __restrict__ c0, float* __restrict__ out) {
    extern __shared__ float sm[];
    float* ws   = sm + WS_OFF;    // [512][64] gate weights, col c = u*4+q
    float* hs   = sm + HS_OFF;    // double-buffered h tile [2][32][130]
    float* xs   = sm + XS_OFF;    // [128][12] x tile
    float* wih  = sm + WIH_OFF;   // [64][12]
    float* bias = sm + BIAS_OFF;  // [64] = b_ih + b_hh

    const int tid = threadIdx.x;
    const int bx  = blockIdx.x;
    const int mi = bx >> 5, ji = bx & 31;
    const int m0 = mi * MT;
    const int j0 = ji * JT;
    const int tx = tid & 15;      // hidden unit within block
    const int ty = tid >> 4;      // row group (0..15)
    const int r0 = ty * 8;
    const int lane = tid & 31;
    const int wid  = tid >> 5;

    // ---- one-time loads (weights resident in smem for the whole run) ----
    for (int idx = tid; idx < CT * HID; idx += NTHREADS) {
        int c = idx >> 9;
        int k = idx & 511;
        int g = (c & 3) * HID + j0 + (c >> 2);
        ws[k * CT + c] = W_hh[(size_t)g * HID + k];
    }
    for (int idx = tid; idx < CT * DDIM; idx += NTHREADS) {
        int c = idx / DDIM, d = idx - c * DDIM;
        int g = (c & 3) * HID + j0 + (c >> 2);
        wih[c * XS_STRIDE + d] = W_ih[g * DDIM + d];
    }
    for (int c = tid; c < CT; c += NTHREADS) {
        int g = (c & 3) * HID + j0 + (c >> 2);
        bias[c] = b_ih[g] + b_hh[g];
    }
    // init h buffer 0 with broadcast h0 (this CTA's owned region)
    for (int idx = tid; idx < MT * JT; idx += NTHREADS) {
        int r = idx >> 4;
        int j = idx & 15;
        g_h[0][(size_t)(m0 + r) * HID + j0 + j] = h0[j0 + j];
    }
    float c_reg[8];
    {
        float ci = c0[j0 + tx];
#pragma unroll
        for (int r = 0; r < 8; ++r) c_reg[r] = ci;
    }
    __syncthreads();
    grid_sync();

    // ---- time loop: 257 encode + 256 decode ----
    for (int s = 0; s < NSTEPS; ++s) {
        const int rb = s & 1;
        const float* __restrict__ hin  = g_h[rb];
        float* __restrict__       hout = g_h[rb ^ 1];

        float4 pf[4];
        ldg_chunk(pf, hin, m0, 0, tid);          // prefetch chunk 0 early

        if (s >= TENC + 1)                        // emit previous decode step's output
            fc_out(hin, fcW, fcb, out, m0 + (ji << 2), s - (TENC + 1), wid, lane);

        const bool enc = (s < TENC);
        if (enc) {
            for (int idx = tid; idx < MT * DDIM; idx += NTHREADS) {
                int r = idx / DDIM, d = idx - r * DDIM;
                xs[r * XS_STRIDE + d] =
                    x[(size_t)(m0 + r) * (TENC * DDIM) + s * DDIM + d];
            }
        }
        sts_chunk(pf, hs, tid);                   // chunk 0 -> buf 0
        __syncthreads();

        // gate accumulators: 4 row-pairs x 4 gates, packed f32x2 over (even,odd) rows
        ull acc[4][4];
#pragma unroll
        for (int rp = 0; rp < 4; ++rp) {
#pragma unroll
            for (int q = 0; q < 4; ++q) {
                float b = bias[tx * 4 + q];
                float lo = b, hi = b;
                if (enc) {
#pragma unroll
                    for (int d = 0; d < DDIM; ++d) {
                        float w = wih[(tx * 4 + q) * XS_STRIDE + d];
                        lo += xs[(r0 + 2 * rp) * XS_STRIDE + d] * w;
                        hi += xs[(r0 + 2 * rp + 1) * XS_STRIDE + d] * w;
                    }
                }
                acc[rp][q] = pack2(lo, hi);
            }
        }

        // main GEMM: gates[128x64] += h[128x512] * Whh_block[64x512]^T
        for (int ch = 0; ch < NCHUNK; ++ch) {
            if (ch + 1 < NCHUNK) ldg_chunk(pf, hin, m0, (ch + 1) * KC, tid);
            const float* wsb = ws + (ch * KC) * CT + (tx << 2);
            const float* hsb = hs + (ch & 1) * HS_BUF + r0;
#pragma unroll
            for (int kk = 0; kk < KC; ++kk) {
                float4 b4 = *(const float4*)(wsb + kk * CT);     // LDS.128: i,f,g,o of unit tx
                ull b0 = dup2(b4.x), b1 = dup2(b4.y), b2 = dup2(b4.z), b3 = dup2(b4.w);
                const ull* ap = (const ull*)(hsb + kk * HS_STRIDE);
#pragma unroll
                for (int rp = 0; rp < 4; ++rp) {
                    ull a2 = ap[rp];                              // LDS.64: two batch rows
                    ffma2(acc[rp][0], a2, b0);
                    ffma2(acc[rp][1], a2, b1);
                    ffma2(acc[rp][2], a2, b2);
                    ffma2(acc[rp][3], a2, b3);
                }
            }
            if (ch + 1 < NCHUNK) sts_chunk(pf, hs + ((ch + 1) & 1) * HS_BUF, tid);
            __syncthreads();
        }

        // pointwise LSTM cell update (CTA-local: this CTA owns (rows, units) block)
#pragma unroll
        for (int rp = 0; rp < 4; ++rp) {
            float ie, io, fe, fo, ge, go, oe, oo;
            unpack2(acc[rp][0], ie, io);
            unpack2(acc[rp][1], fe, fo);
            unpack2(acc[rp][2], ge, go);
            unpack2(acc[rp][3], oe, oo);
            float ce = sigf(fe) * c_reg[2 * rp]     + sigf(ie) * tanhf(ge);
            float co = sigf(fo) * c_reg[2 * rp + 1] + sigf(io) * tanhf(go);
            c_reg[2 * rp]     = ce;
            c_reg[2 * rp + 1] = co;
            float he = sigf(oe) * tanhf(ce);
            float ho = sigf(oo) * tanhf(co);
            hout[(size_t)(m0 + r0 + 2 * rp)     * HID + j0 + tx] = he;
            hout[(size_t)(m0 + r0 + 2 * rp + 1) * HID + j0 + tx] = ho;
        }
        grid_sync();
    }

    // final decode step's output
    fc_out(g_h[NSTEPS & 1], fcW, fcb, out, m0 + (ji << 2), TDEC - 1, wid, lane);
}

// ---------------- launch ----------------
extern "C" void kernel_launch(void* const* d_in, const int* in_sizes, int n_in,
                              void* d_out, int out_size) {
    (void)in_sizes; (void)n_in; (void)out_size;
    cudaFuncSetAttribute(lstm_kernel, cudaFuncAttributeMaxDynamicSharedMemorySize,
                         SMEM_BYTES);
    lstm_kernel<<<NCTA, NTHREADS, SMEM_BYTES>>>(
        (const float*)d_in[0],   // x
        (const float*)d_in[1],   // W_ih
        (const float*)d_in[2],   // W_hh
        (const float*)d_in[3],   // b_ih
        (const float*)d_in[4],   // b_hh
        (const float*)d_in[5],   // fc_W
        (const float*)d_in[6],   // fc_b
        (const float*)d_in[7],   // h0
        (const float*)d_in[8],   // c0
        (float*)d_out);
}

// round 3
// speedup vs baseline: 1.0033x; 1.0033x over previous
#include <cuda_runtime.h>

// ---------------- problem constants ----------------
#define NBATCH 512
#define HID    512
#define GATES  2048           // 4*HID
#define DDIM   9
#define TENC   257            // encode steps (T+1)
#define TDEC   256            // decode steps
#define NSTEPS 513            // TENC + TDEC

// ---------------- tiling ----------------
#define MB 4                  // batch blocks
#define JB 32                 // hidden-unit blocks
#define NCTA (MB*JB)          // 128 CTAs, 1 per SM, all resident
#define MT 128                // batch rows per CTA
#define JT 16                 // hidden units per CTA
#define CT 64                 // gate columns per CTA = 4*JT
#define KC 32                 // k-chunk
#define NCHUNK (HID/KC)       // 16
#define NTHREADS 256

#define HS_STRIDE 130         // padded row stride for h tile (conflict-free, even for 8B loads)
#define HS_BUF (KC*HS_STRIDE)
#define XS_STRIDE 12

// smem layout in floats
#define WS_OFF   0
#define HS_OFF   (WS_OFF + HID*CT)            // 32768
#define XS_OFF   (HS_OFF + 2*HS_BUF)          // +8320
#define WIH_OFF  (XS_OFF + MT*XS_STRIDE)      // +1536
#define BIAS_OFF (WIH_OFF + CT*XS_STRIDE)     // +768
#define SMEM_FLOATS (BIAS_OFF + CT)
#define SMEM_BYTES  (SMEM_FLOATS*4)           // 173,824 B

typedef unsigned long long ull;

// ---------------- device globals ----------------
__device__ __align__(16) float g_h[2][NBATCH*HID];   // double-buffered hidden state
__device__ unsigned g_cnt = 0;
__device__ unsigned g_gen = 0;

// ---------------- helpers ----------------
__device__ __forceinline__ float sigf(float x) { return 1.0f / (1.0f + __expf(-x)); }

__device__ __forceinline__ ull pack2(float lo, float hi) {
    ull r; asm("mov.b64 %0, {%1,%2};" : "=l"(r) : "f"(lo), "f"(hi)); return r;
}
__device__ __forceinline__ void unpack2(ull v, float& lo, float& hi) {
    asm("mov.b64 {%0,%1}, %2;" : "=f"(lo), "=f"(hi) : "l"(v));
}
__device__ __forceinline__ ull dup2(float x) {
    ull r; asm("mov.b64 %0, {%1,%1};" : "=l"(r) : "f"(x)); return r;
}
__device__ __forceinline__ void ffma2(ull& acc, ull a, ull b) {
    asm("fma.rn.f32x2 %0, %1, %2, %0;" : "+l"(acc) : "l"(a), "l"(b));
}

__device__ __forceinline__ void grid_sync() {
    __syncthreads();
    if (threadIdx.x == 0) {
        __threadfence();
        volatile unsigned* genp = &g_gen;
        unsigned target = *genp + 1u;
        if (atomicAdd(&g_cnt, 1u) == NCTA - 1u) {
            atomicExch(&g_cnt, 0u);
            __threadfence();
            atomicExch(&g_gen, target);
        } else {
            while ((int)(*genp - target) < 0) { }
        }
        __threadfence();
    }
    __syncthreads();
}

// prefetch one 128x32 chunk of h into registers (coalesced float4, L2 path)
__device__ __forceinline__ void ldg_chunk(float4* pf, const float* __restrict__ hin,
                                          int m0, int k0, int tid) {
    int rr = tid >> 3;              // 0..31
    int k4 = (tid & 7) << 2;        // 0,4,...,28
    const float4* base = (const float4*)(hin + (size_t)(m0 + rr) * HID + k0 + k4);
#pragma unroll
    for (int i = 0; i < 4; ++i)
        pf[i] = __ldcg(base + (size_t)i * 32 * (HID / 4));
}
// store chunk transposed into smem: hs[k][row], stride 130 (conflict-free-ish)
__device__ __forceinline__ void sts_chunk(const float4* pf, float* hbuf, int tid) {
    int rr = tid >> 3;
    int k4 = (tid & 7) << 2;
#pragma unroll
    for (int i = 0; i < 4; ++i) {
        int row = rr + i * 32;
        hbuf[(k4 + 0) * HS_STRIDE + row] = pf[i].x;
        hbuf[(k4 + 1) * HS_STRIDE + row] = pf[i].y;
        hbuf[(k4 + 2) * HS_STRIDE + row] = pf[i].z;
        hbuf[(k4 + 3) * HS_STRIDE + row] = pf[i].w;
    }
}

// FC head: 4 rows x 9 outputs per CTA, one output per warp-slot, lane-parallel over k
__device__ __forceinline__ void fc_out(const float* __restrict__ h,
                                       const float* __restrict__ fcW,
                                       const float* __restrict__ fcb,
                                       float* __restrict__ out,
                                       int n0, int td, int wid, int lane) {
    for (int o = wid; o < 4 * DDIM; o += 8) {
        int rr = o / DDIM, d = o - rr * DDIM;
        int n = n0 + rr;
        const float* hr = h + (size_t)n * HID;
        const float* wr = fcW + d * HID;
        float s = 0.0f;
#pragma unroll
        for (int j = 0; j < 16; ++j)
            s += __ldcg(hr + j * 32 + lane) * wr[j * 32 + lane];
#pragma unroll
        for (int off = 16; off; off >>= 1)
            s += __shfl_xor_sync(0xffffffffu, s, off);
        if (lane == 0)
            out[((size_t)n * TDEC + td) * DDIM + d] = sigf(s + fcb[d]);
    }
}

// ---------------- persistent kernel ----------------
__global__ void __launch_bounds__(NTHREADS, 1)
lstm_kernel(const float* __restrict__ x, const float* __restrict__ W_ih,
            const float* __restrict__ W_hh, const float* __restrict__ b_ih,
            const float* __restrict__ b_hh, const float* __restrict__ fcW,
            const float* __restrict__ fcb, const float* __restrict__ h0,
            const float* __restrict__ c0, float* __restrict__ out) {
    extern __shared__ float sm[];
    float* ws   = sm + WS_OFF;    // [512][64] gate weights, col c = u*4+q
    float* hs   = sm + HS_OFF;    // double-buffered h tile [2][32][130]
    float* xs   = sm + XS_OFF;    // [128][12] x tile
    float* wih  = sm + WIH_OFF;   // [64][12]
    float* bias = sm + BIAS_OFF;  // [64] = b_ih + b_hh

    const int tid = threadIdx.x;
    const int bx  = blockIdx.x;
    const int mi = bx >> 5, ji = bx & 31;
    const int m0 = mi * MT;
    const int j0 = ji * JT;
    const int tx = tid & 15;      // hidden unit within block
    const int ty = tid >> 4;      // row group (0..15)
    const int r0 = ty * 8;
    const int lane = tid & 31;
    const int wid  = tid >> 5;

    // ---- one-time loads (weights resident in smem for the whole run) ----
    for (int idx = tid; idx < CT * HID; idx += NTHREADS) {
        int c = idx >> 9;
        int k = idx & 511;
        int g = (c & 3) * HID + j0 + (c >> 2);
        ws[k * CT + c] = W_hh[(size_t)g * HID + k];
    }
    for (int idx = tid; idx < CT * DDIM; idx += NTHREADS) {
        int c = idx / DDIM, d = idx - c * DDIM;
        int g = (c & 3) * HID + j0 + (c >> 2);
        wih[c * XS_STRIDE + d] = W_ih[g * DDIM + d];
    }
    for (int c = tid; c < CT; c += NTHREADS) {
        int g = (c & 3) * HID + j0 + (c >> 2);
        bias[c] = b_ih[g] + b_hh[g];
    }
    // init h buffer 0 with broadcast h0 (this CTA's owned region)
    for (int idx = tid; idx < MT * JT; idx += NTHREADS) {
        int r = idx >> 4;
        int j = idx & 15;
        g_h[0][(size_t)(m0 + r) * HID + j0 + j] = h0[j0 + j];
    }
    float c_reg[8];
    {
        float ci = c0[j0 + tx];
#pragma unroll
        for (int r = 0; r < 8; ++r) c_reg[r] = ci;
    }
    __syncthreads();
    grid_sync();

    // ---- time loop: 257 encode + 256 decode ----
    for (int s = 0; s < NSTEPS; ++s) {
        const int rb = s & 1;
        const float* __restrict__ hin  = g_h[rb];
        float* __restrict__       hout = g_h[rb ^ 1];

        float4 pf[4];
        ldg_chunk(pf, hin, m0, 0, tid);          // prefetch chunk 0 early

        if (s >= TENC + 1)                        // emit previous decode step's output
            fc_out(hin, fcW, fcb, out, m0 + (ji << 2), s - (TENC + 1), wid, lane);

        const bool enc = (s < TENC);
        if (enc) {
            for (int idx = tid; idx < MT * DDIM; idx += NTHREADS) {
                int r = idx / DDIM, d = idx - r * DDIM;
                xs[r * XS_STRIDE + d] =
                    x[(size_t)(m0 + r) * (TENC * DDIM) + s * DDIM + d];
            }
        }
        sts_chunk(pf, hs, tid);                   // chunk 0 -> buf 0
        __syncthreads();

        // gate accumulators: 4 row-pairs x 4 gates, packed f32x2 over (even,odd) rows
        ull acc[4][4];
#pragma unroll
        for (int rp = 0; rp < 4; ++rp) {
#pragma unroll
            for (int q = 0; q < 4; ++q) {
                float b = bias[tx * 4 + q];
                float lo = b, hi = b;
                if (enc) {
#pragma unroll
                    for (int d = 0; d < DDIM; ++d) {
                        float w = wih[(tx * 4 + q) * XS_STRIDE + d];
                        lo += xs[(r0 + 2 * rp) * XS_STRIDE + d] * w;
                        hi += xs[(r0 + 2 * rp + 1) * XS_STRIDE + d] * w;
                    }
                }
                acc[rp][q] = pack2(lo, hi);
            }
        }

        // main GEMM: gates[128x64] += h[128x512] * Whh_block[64x512]^T
        for (int ch = 0; ch < NCHUNK; ++ch) {
            if (ch + 1 < NCHUNK) ldg_chunk(pf, hin, m0, (ch + 1) * KC, tid);
            const float* wsb = ws + (ch * KC) * CT + (tx << 2);
            const float* hsb = hs + (ch & 1) * HS_BUF + r0;
#pragma unroll
            for (int kk = 0; kk < KC; ++kk) {
                float4 b4 = *(const float4*)(wsb + kk * CT);     // LDS.128: i,f,g,o of unit tx
                ull b0 = dup2(b4.x), b1 = dup2(b4.y), b2 = dup2(b4.z), b3 = dup2(b4.w);
                const ull* ap = (const ull*)(hsb + kk * HS_STRIDE);
#pragma unroll
                for (int rp = 0; rp < 4; ++rp) {
                    ull a2 = ap[rp];                              // LDS.64: two batch rows
                    ffma2(acc[rp][0], a2, b0);
                    ffma2(acc[rp][1], a2, b1);
                    ffma2(acc[rp][2], a2, b2);
                    ffma2(acc[rp][3], a2, b3);
                }
            }
            if (ch + 1 < NCHUNK) sts_chunk(pf, hs + ((ch + 1) & 1) * HS_BUF, tid);
            __syncthreads();
        }

        // pointwise LSTM cell update (CTA-local: this CTA owns (rows, units) block)
#pragma unroll
        for (int rp = 0; rp < 4; ++rp) {
            float ie, io, fe, fo, ge, go, oe, oo;
            unpack2(acc[rp][0], ie, io);
            unpack2(acc[rp][1], fe, fo);
            unpack2(acc[rp][2], ge, go);
            unpack2(acc[rp][3], oe, oo);
            float ce = sigf(fe) * c_reg[2 * rp]     + sigf(ie) * tanhf(ge);
            float co = sigf(fo) * c_reg[2 * rp + 1] + sigf(io) * tanhf(go);
            c_reg[2 * rp]     = ce;
            c_reg[2 * rp + 1] = co;
            float he = sigf(oe) * tanhf(ce);
            float ho = sigf(oo) * tanhf(co);
            hout[(size_t)(m0 + r0 + 2 * rp)     * HID + j0 + tx] = he;
            hout[(size_t)(m0 + r0 + 2 * rp + 1) * HID + j0 + tx] = ho;
        }
        grid_sync();
    }

    // final decode step's output
    fc_out(g_h[NSTEPS & 1], fcW, fcb, out, m0 + (ji << 2), TDEC - 1, wid, lane);
}

// ---------------- launch ----------------
extern "C" void kernel_launch(void* const* d_in, const int* in_sizes, int n_in,
                              void* d_out, int out_size) {
    (void)in_sizes; (void)n_in; (void)out_size;
    cudaFuncSetAttribute(lstm_kernel, cudaFuncAttributeMaxDynamicSharedMemorySize,
                         SMEM_BYTES);
    lstm_kernel<<<NCTA, NTHREADS, SMEM_BYTES>>>(
        (const float*)d_in[0],   // x
        (const float*)d_in[1],   // W_ih
        (const float*)d_in[2],   // W_hh
        (const float*)d_in[3],   // b_ih
        (const float*)d_in[4],   // b_hh
        (const float*)d_in[5],   // fc_W
        (const float*)d_in[6],   // fc_b
        (const float*)d_in[7],   // h0
        (const float*)d_in[8],   // c0
        (float*)d_out);
}